// round 5
// baseline (speedup 1.0000x reference)
#include <cuda_runtime.h>
#include <cstdint>
#include <math.h>

#define T_STEPS 512
#define BATCH   64
#define DIN     256
#define HID     512
#define NGATE4  2048   // 4*H
#define KDH     768    // D+H

#define HP       132   // h chunk row pitch (128 cols + 4 pad)
#define WT_P     18    // transposed weight pitch: 16 rows + 2 pad
#define GS_PITCH 17

// -------- device scratch --------
__device__ float g_xg[(size_t)T_STEPS * BATCH * NGATE4];
__device__ float g_h[2][BATCH * HID];
__device__ unsigned int g_ctr;

__device__ __forceinline__ float fsigm(float x) {
    return __fdividef(1.0f, 1.0f + __expf(-x));
}
__device__ __forceinline__ float ftanh(float x) {
    float e = __expf(2.0f * x);
    return 1.0f - __fdividef(2.0f, e + 1.0f);
}

// ---- packed fp32x2 helpers ----
__device__ __forceinline__ unsigned long long dup2(float x) {
    unsigned long long r;
    unsigned int xi = __float_as_uint(x);
    asm("mov.b64 %0, {%1, %1};" : "=l"(r) : "r"(xi));
    return r;
}
__device__ __forceinline__ unsigned long long pack2(float lo, float hi) {
    unsigned long long r;
    unsigned int l = __float_as_uint(lo), h = __float_as_uint(hi);
    asm("mov.b64 %0, {%1, %2};" : "=l"(r) : "r"(l), "r"(h));
    return r;
}
__device__ __forceinline__ void fma2(unsigned long long& d,
                                     unsigned long long a, unsigned long long b) {
    asm("fma.rn.f32x2 %0, %1, %2, %0;" : "+l"(d) : "l"(a), "l"(b));
}
__device__ __forceinline__ void unpack2(unsigned long long v, float& lo, float& hi) {
    unsigned int l, h;
    asm("mov.b64 {%0, %1}, %2;" : "=r"(l), "=r"(h) : "l"(v));
    lo = __uint_as_float(l);
    hi = __uint_as_float(h);
}

// -------- init --------
__global__ void init_kernel() {
    int idx = blockIdx.x * blockDim.x + threadIdx.x;
    if (idx == 0) g_ctr = 0u;
    int total = 2 * BATCH * HID;
    for (int i = idx; i < total; i += gridDim.x * blockDim.x)
        ((float*)g_h)[i] = 0.0f;
}

// -------- kernel 1: xg = X @ W[:, :D]^T + b  (f32x2, double-buffered) --------
__global__ __launch_bounds__(256) void xgemm_kernel(
    const float* __restrict__ X,
    const float* __restrict__ Wf, const float* __restrict__ bf,
    const float* __restrict__ Wi, const float* __restrict__ bi,
    const float* __restrict__ Wg, const float* __restrict__ bg,
    const float* __restrict__ Wo, const float* __restrict__ bo)
{
    __shared__ float As[2][8][128];
    __shared__ float Bs[2][8][128];

    const int tid   = threadIdx.x;
    const int nBase = blockIdx.x * 128;
    const int mBase = blockIdx.y * 128;
    const int gate  = nBase >> 9;
    const float* W    = (gate == 0) ? Wf : (gate == 1) ? Wi : (gate == 2) ? Wg : Wo;
    const float* bias = (gate == 0) ? bf : (gate == 1) ? bi : (gate == 2) ? bg : bo;

    const int loadRow = tid >> 1;
    const int loadCol = (tid & 1) * 4;
    const float* pA = X + (size_t)(mBase + loadRow) * DIN + loadCol;
    const int wrow  = (nBase + loadRow) & 511;
    const float* pB = W + (size_t)wrow * KDH + loadCol;

    float4 a = *(const float4*)pA;
    float4 b = *(const float4*)pB;

    const int tx = tid & 15, ty = tid >> 4;

    unsigned long long acc2[8][4];
#pragma unroll
    for (int i = 0; i < 8; ++i)
#pragma unroll
        for (int j = 0; j < 4; ++j) acc2[i][j] = 0ULL;

    As[0][loadCol + 0][loadRow] = a.x; As[0][loadCol + 1][loadRow] = a.y;
    As[0][loadCol + 2][loadRow] = a.z; As[0][loadCol + 3][loadRow] = a.w;
    Bs[0][loadCol + 0][loadRow] = b.x; Bs[0][loadCol + 1][loadRow] = b.y;
    Bs[0][loadCol + 2][loadRow] = b.z; Bs[0][loadCol + 3][loadRow] = b.w;
    __syncthreads();

    for (int kt = 0; kt < 32; ++kt) {
        const int cur = kt & 1;
        if (kt < 31) {
            a = *(const float4*)(pA + (kt + 1) * 8);
            b = *(const float4*)(pB + (kt + 1) * 8);
        }
#pragma unroll
        for (int k = 0; k < 8; ++k) {
            float ar[8], br[8];
            *(float4*)&ar[0] = *(const float4*)&As[cur][k][ty * 4];
            *(float4*)&ar[4] = *(const float4*)&As[cur][k][64 + ty * 4];
            *(float4*)&br[0] = *(const float4*)&Bs[cur][k][tx * 4];
            *(float4*)&br[4] = *(const float4*)&Bs[cur][k][64 + tx * 4];
            unsigned long long ad[8], b2[4];
#pragma unroll
            for (int i = 0; i < 8; ++i) ad[i] = dup2(ar[i]);
#pragma unroll
            for (int j = 0; j < 4; ++j) b2[j] = pack2(br[2 * j], br[2 * j + 1]);
#pragma unroll
            for (int i = 0; i < 8; ++i)
#pragma unroll
                for (int j = 0; j < 4; ++j)
                    fma2(acc2[i][j], ad[i], b2[j]);
        }
        if (kt < 31) {
            const int nxt = cur ^ 1;
            As[nxt][loadCol + 0][loadRow] = a.x; As[nxt][loadCol + 1][loadRow] = a.y;
            As[nxt][loadCol + 2][loadRow] = a.z; As[nxt][loadCol + 3][loadRow] = a.w;
            Bs[nxt][loadCol + 0][loadRow] = b.x; Bs[nxt][loadCol + 1][loadRow] = b.y;
            Bs[nxt][loadCol + 2][loadRow] = b.z; Bs[nxt][loadCol + 3][loadRow] = b.w;
            __syncthreads();
        }
    }

    float bv[8];
#pragma unroll
    for (int j = 0; j < 8; ++j) {
        int nn = (j < 4) ? (tx * 4 + j) : (64 + tx * 4 + (j - 4));
        bv[j] = bias[(nBase + nn) & 511];
    }
#pragma unroll
    for (int i = 0; i < 8; ++i) {
        int mm = (i < 4) ? (ty * 4 + i) : (64 + ty * 4 + (i - 4));
        float* o = g_xg + (size_t)(mBase + mm) * NGATE4 + nBase;
        float v[8];
#pragma unroll
        for (int j = 0; j < 4; ++j) unpack2(acc2[i][j], v[2 * j], v[2 * j + 1]);
        float4 v0 = make_float4(v[0] + bv[0], v[1] + bv[1], v[2] + bv[2], v[3] + bv[3]);
        float4 v1 = make_float4(v[4] + bv[4], v[5] + bv[5], v[6] + bv[6], v[7] + bv[7]);
        *(float4*)&o[tx * 4]      = v0;
        *(float4*)&o[64 + tx * 4] = v1;
    }
}

// -------- kernel 2: persistent recurrent loop, 128 CTAs x 256 threads --------
__global__ __launch_bounds__(256, 1) void lstm_rec_kernel(
    const float* __restrict__ Wf, const float* __restrict__ Wi,
    const float* __restrict__ Wg, const float* __restrict__ Wo,
    float* __restrict__ out)
{
    extern __shared__ float smem[];
    float* hb  = smem;                           // [2][64*HP]
    float* Wst = smem + 2 * 64 * HP;             // transposed weights [512][WT_P]
    float* gs  = Wst + 512 * WT_P;               // [64][GS_PITCH]

    const int tid = threadIdx.x;
    const int cb  = blockIdx.x;
    const int u0  = cb * 4;

    // --- load + transpose recurrent weight slice into Wst[k][r] ---
    {
        for (int it = 0; it < 8; ++it) {
            int f4 = it * 256 + tid;           // 0..2047
            int r  = f4 >> 7;                  // 0..15
            int k0 = (f4 & 127) * 4;
            int gg = r >> 2, j = r & 3;
            const float* Wp = (gg == 0) ? Wf : (gg == 1) ? Wi : (gg == 2) ? Wg : Wo;
            float4 v = *(const float4*)(Wp + (size_t)(u0 + j) * KDH + DIN + k0);
            Wst[(k0 + 0) * WT_P + r] = v.x;
            Wst[(k0 + 1) * WT_P + r] = v.y;
            Wst[(k0 + 2) * WT_P + r] = v.z;
            Wst[(k0 + 3) * WT_P + r] = v.w;
        }
    }
    __syncthreads();

    const int kp = tid & 15;
    const int rq = (tid >> 4) & 1;
    const int bq = tid >> 5;
    const int eb = tid >> 2;
    const int ej = tid & 3;

    const bool hi0 = (kp & 1);
    const bool hi1 = ((kp >> 1) & 1);
    const bool hi2 = ((kp >> 2) & 1);
    const bool hi3 = ((kp >> 3) & 1);

    float c_reg = 0.0f;
    float h_last = 0.0f;

    for (int t = 0; t < T_STEPS; ++t) {
        const float* xr = g_xg + (size_t)(t * BATCH + eb) * NGATE4 + u0 + ej;
        float xf = xr[0 * HID], xi = xr[1 * HID], xg2 = xr[2 * HID], xo = xr[3 * HID];

        if (t > 0) {
            if (tid == 0) {
                unsigned target = (unsigned)t * 128u;
                while (*(volatile unsigned*)&g_ctr < target) { }
            }
            __syncthreads();
            __threadfence();
        }

        const float* hin = g_h[t & 1];

        // ---- stage chunk 0 ----
        float4 pre[8];
#pragma unroll
        for (int i = 0; i < 8; ++i) {
            int f4 = i * 256 + tid;
            int b  = f4 >> 5;
            int kq = (f4 & 31) * 4;
            pre[i] = *(const float4*)(hin + b * HID + kq);
        }
#pragma unroll
        for (int i = 0; i < 8; ++i) {
            int f4 = i * 256 + tid;
            int b  = f4 >> 5;
            int kq = (f4 & 31) * 4;
            *(float4*)&hb[b * HP + kq] = pre[i];
        }
        __syncthreads();

        unsigned long long acc2[8][4];
#pragma unroll
        for (int i = 0; i < 8; ++i)
#pragma unroll
            for (int j = 0; j < 4; ++j) acc2[i][j] = 0ULL;

        // ---- pipelined K-chunk loop (4 chunks of 128) ----
        for (int c = 0; c < 4; ++c) {
            if (c < 3) {
#pragma unroll
                for (int i = 0; i < 8; ++i) {
                    int f4 = i * 256 + tid;
                    int b  = f4 >> 5;
                    int kq = (f4 & 31) * 4;
                    pre[i] = *(const float4*)(hin + b * HID + (c + 1) * 128 + kq);
                }
            }
            const float* hp = hb + (c & 1) * (64 * HP) + (bq * 8) * HP + kp;
            const float* wt = Wst + (c * 128 + kp) * WT_P + rq * 8;
#pragma unroll
            for (int g8 = 0; g8 < 8; ++g8) {
                float hv[8];
#pragma unroll
                for (int jb = 0; jb < 8; ++jb) hv[jb] = hp[jb * HP + g8 * 16];
                unsigned long long wv2[4];
#pragma unroll
                for (int jp = 0; jp < 4; ++jp)
                    wv2[jp] = *(const unsigned long long*)(wt + g8 * 16 * WT_P + 2 * jp);
                unsigned long long hd[8];
#pragma unroll
                for (int jb = 0; jb < 8; ++jb) hd[jb] = dup2(hv[jb]);
#pragma unroll
                for (int jb = 0; jb < 8; ++jb)
#pragma unroll
                    for (int jp = 0; jp < 4; ++jp)
                        fma2(acc2[jb][jp], hd[jb], wv2[jp]);
            }
            if (c < 3) {
                float* b2 = hb + ((c + 1) & 1) * (64 * HP);
#pragma unroll
                for (int i = 0; i < 8; ++i) {
                    int f4 = i * 256 + tid;
                    int b  = f4 >> 5;
                    int kq = (f4 & 31) * 4;
                    *(float4*)&b2[b * HP + kq] = pre[i];
                }
                __syncthreads();
            }
        }

        // ---- unpack to scalar grid ----
        float acc[8][8];
#pragma unroll
        for (int jb = 0; jb < 8; ++jb)
#pragma unroll
            for (int jp = 0; jp < 4; ++jp)
                unpack2(acc2[jb][jp], acc[jb][2 * jp], acc[jb][2 * jp + 1]);

        // ---- value-splitting butterfly over 16 kp lanes ----
        float a2[4][8];
#pragma unroll
        for (int p = 0; p < 4; ++p)
#pragma unroll
            for (int jr = 0; jr < 8; ++jr) {
                float sv = hi0 ? acc[2 * p][jr] : acc[2 * p + 1][jr];
                float kv = hi0 ? acc[2 * p + 1][jr] : acc[2 * p][jr];
                a2[p][jr] = kv + __shfl_xor_sync(0xffffffffu, sv, 1);
            }
        float a3[2][8];
#pragma unroll
        for (int q = 0; q < 2; ++q)
#pragma unroll
            for (int jr = 0; jr < 8; ++jr) {
                float sv = hi1 ? a2[2 * q][jr] : a2[2 * q + 1][jr];
                float kv = hi1 ? a2[2 * q + 1][jr] : a2[2 * q][jr];
                a3[q][jr] = kv + __shfl_xor_sync(0xffffffffu, sv, 2);
            }
        float a4[8];
#pragma unroll
        for (int jr = 0; jr < 8; ++jr) {
            float sv = hi2 ? a3[0][jr] : a3[1][jr];
            float kv = hi2 ? a3[1][jr] : a3[0][jr];
            a4[jr] = kv + __shfl_xor_sync(0xffffffffu, sv, 4);
        }
        float rr[4];
#pragma unroll
        for (int jrr = 0; jrr < 4; ++jrr) {
            float sv = hi3 ? a4[jrr] : a4[jrr + 4];
            float kv = hi3 ? a4[jrr + 4] : a4[jrr];
            rr[jrr] = kv + __shfl_xor_sync(0xffffffffu, sv, 8);
        }
        {
            int row  = bq * 8 + (kp & 7);
            int col0 = rq * 8 + (kp >> 3) * 4;
#pragma unroll
            for (int jrr = 0; jrr < 4; ++jrr)
                gs[row * GS_PITCH + col0 + jrr] = rr[jrr];
        }
        __syncthreads();

        // ---- elementwise LSTM cell ----
        float pf = gs[eb * GS_PITCH + 0  + ej] + xf;
        float pi = gs[eb * GS_PITCH + 4  + ej] + xi;
        float pg = gs[eb * GS_PITCH + 8  + ej] + xg2;
        float po = gs[eb * GS_PITCH + 12 + ej] + xo;
        float fg = fsigm(pf);
        float ig = fsigm(pi);
        float gg = ftanh(pg);
        float og = fsigm(po);
        c_reg = fg * c_reg + ig * gg;
        float hv = og * ftanh(c_reg);
        h_last = hv;

        out[(size_t)t * (BATCH * HID) + eb * HID + u0 + ej] = hv;
        g_h[(t + 1) & 1][eb * HID + u0 + ej] = hv;

        __threadfence();
        __syncthreads();
        if (tid == 0) atomicAdd(&g_ctr, 1u);
    }

    const size_t off = (size_t)T_STEPS * BATCH * HID;
    out[off + eb * HID + u0 + ej]               = h_last;
    out[off + BATCH * HID + eb * HID + u0 + ej] = c_reg;
}

extern "C" void kernel_launch(void* const* d_in, const int* in_sizes, int n_in,
                              void* d_out, int out_size) {
    const float* X  = (const float*)d_in[0];
    const float* Wf = (const float*)d_in[1];
    const float* bf = (const float*)d_in[2];
    const float* Wi = (const float*)d_in[3];
    const float* bi = (const float*)d_in[4];
    const float* Wg = (const float*)d_in[5];
    const float* bg = (const float*)d_in[6];
    const float* Wo = (const float*)d_in[7];
    const float* bo = (const float*)d_in[8];
    float* out = (float*)d_out;

    const int smem_bytes = (2 * 64 * HP + 512 * WT_P + 64 * GS_PITCH) * 4;
    cudaFuncSetAttribute(lstm_rec_kernel,
                         cudaFuncAttributeMaxDynamicSharedMemorySize, smem_bytes);

    init_kernel<<<64, 256>>>();
    xgemm_kernel<<<dim3(16, 256), 256>>>(X, Wf, bf, Wi, bi, Wg, bg, Wo, bo);
    lstm_rec_kernel<<<128, 256, smem_bytes>>>(Wf, Wi, Wg, Wo, out);
}

// round 6
// speedup vs baseline: 1.0788x; 1.0788x over previous
#include <cuda_runtime.h>
#include <cstdint>
#include <math.h>

#define T_STEPS 512
#define BATCH   64
#define DIN     256
#define HID     512
#define NGATE4  2048   // 4*H
#define KDH     768    // D+H

#define HP       132   // h chunk row pitch
#define WS_PITCH 516
#define GS_PITCH 17

// -------- device scratch --------
__device__ float g_xg[(size_t)T_STEPS * BATCH * NGATE4];
__device__ float g_h[2][BATCH * HID];
__device__ unsigned int g_ctr;

__device__ __forceinline__ float fsigm(float x) {
    return __fdividef(1.0f, 1.0f + __expf(-x));
}
__device__ __forceinline__ float ftanh(float x) {
    float e = __expf(2.0f * x);
    return 1.0f - __fdividef(2.0f, e + 1.0f);
}

// -------- init --------
__global__ void init_kernel() {
    int idx = blockIdx.x * blockDim.x + threadIdx.x;
    if (idx == 0) g_ctr = 0u;
    int total = 2 * BATCH * HID;
    for (int i = idx; i < total; i += gridDim.x * blockDim.x)
        ((float*)g_h)[i] = 0.0f;
}

// -------- kernel 1: xg = X @ W[:, :D]^T + b (scalar FFMA, double-buffered) ----
__global__ __launch_bounds__(256) void xgemm_kernel(
    const float* __restrict__ X,
    const float* __restrict__ Wf, const float* __restrict__ bf,
    const float* __restrict__ Wi, const float* __restrict__ bi,
    const float* __restrict__ Wg, const float* __restrict__ bg,
    const float* __restrict__ Wo, const float* __restrict__ bo)
{
    __shared__ float As[2][8][128];
    __shared__ float Bs[2][8][128];

    const int tid   = threadIdx.x;
    const int nBase = blockIdx.x * 128;
    const int mBase = blockIdx.y * 128;
    const int gate  = nBase >> 9;
    const float* W    = (gate == 0) ? Wf : (gate == 1) ? Wi : (gate == 2) ? Wg : Wo;
    const float* bias = (gate == 0) ? bf : (gate == 1) ? bi : (gate == 2) ? bg : bo;

    const int loadRow = tid >> 1;
    const int loadCol = (tid & 1) * 4;
    const float* pA = X + (size_t)(mBase + loadRow) * DIN + loadCol;
    const int wrow  = (nBase + loadRow) & 511;
    const float* pB = W + (size_t)wrow * KDH + loadCol;

    float4 a = *(const float4*)pA;
    float4 b = *(const float4*)pB;

    const int tx = tid & 15, ty = tid >> 4;

    float acc[8][8];
#pragma unroll
    for (int i = 0; i < 8; ++i)
#pragma unroll
        for (int j = 0; j < 8; ++j) acc[i][j] = 0.0f;

    As[0][loadCol + 0][loadRow] = a.x; As[0][loadCol + 1][loadRow] = a.y;
    As[0][loadCol + 2][loadRow] = a.z; As[0][loadCol + 3][loadRow] = a.w;
    Bs[0][loadCol + 0][loadRow] = b.x; Bs[0][loadCol + 1][loadRow] = b.y;
    Bs[0][loadCol + 2][loadRow] = b.z; Bs[0][loadCol + 3][loadRow] = b.w;
    __syncthreads();

    for (int kt = 0; kt < 32; ++kt) {
        const int cur = kt & 1;
        if (kt < 31) {
            a = *(const float4*)(pA + (kt + 1) * 8);
            b = *(const float4*)(pB + (kt + 1) * 8);
        }
#pragma unroll
        for (int k = 0; k < 8; ++k) {
            float ar[8], br[8];
            *(float4*)&ar[0] = *(const float4*)&As[cur][k][ty * 4];
            *(float4*)&ar[4] = *(const float4*)&As[cur][k][64 + ty * 4];
            *(float4*)&br[0] = *(const float4*)&Bs[cur][k][tx * 4];
            *(float4*)&br[4] = *(const float4*)&Bs[cur][k][64 + tx * 4];
#pragma unroll
            for (int i = 0; i < 8; ++i)
#pragma unroll
                for (int j = 0; j < 8; ++j)
                    acc[i][j] = fmaf(ar[i], br[j], acc[i][j]);
        }
        if (kt < 31) {
            const int nxt = cur ^ 1;
            As[nxt][loadCol + 0][loadRow] = a.x; As[nxt][loadCol + 1][loadRow] = a.y;
            As[nxt][loadCol + 2][loadRow] = a.z; As[nxt][loadCol + 3][loadRow] = a.w;
            Bs[nxt][loadCol + 0][loadRow] = b.x; Bs[nxt][loadCol + 1][loadRow] = b.y;
            Bs[nxt][loadCol + 2][loadRow] = b.z; Bs[nxt][loadCol + 3][loadRow] = b.w;
            __syncthreads();
        }
    }

    float bv[8];
#pragma unroll
    for (int j = 0; j < 8; ++j) {
        int nn = (j < 4) ? (tx * 4 + j) : (64 + tx * 4 + (j - 4));
        bv[j] = bias[(nBase + nn) & 511];
    }
#pragma unroll
    for (int i = 0; i < 8; ++i) {
        int mm = (i < 4) ? (ty * 4 + i) : (64 + ty * 4 + (i - 4));
        float* o = g_xg + (size_t)(mBase + mm) * NGATE4 + nBase;
        float4 v0 = make_float4(acc[i][0] + bv[0], acc[i][1] + bv[1],
                                acc[i][2] + bv[2], acc[i][3] + bv[3]);
        float4 v1 = make_float4(acc[i][4] + bv[4], acc[i][5] + bv[5],
                                acc[i][6] + bv[6], acc[i][7] + bv[7]);
        *(float4*)&o[tx * 4]      = v0;
        *(float4*)&o[64 + tx * 4] = v1;
    }
}

// -------- kernel 2: persistent recurrent loop, 128 CTAs x 256 threads --------
__global__ __launch_bounds__(256, 1) void lstm_rec_kernel(
    const float* __restrict__ Wf, const float* __restrict__ Wi,
    const float* __restrict__ Wg, const float* __restrict__ Wo,
    float* __restrict__ out)
{
    extern __shared__ float smem[];
    float* hb = smem;                                  // [2][64*HP]
    float* Ws = smem + 2 * 64 * HP;                    // [16][WS_PITCH] (+16 pad upper half)
    float* gs = Ws + 16 * WS_PITCH + 16;               // [64][GS_PITCH]

    const int tid = threadIdx.x;
    const int cb  = blockIdx.x;
    const int u0  = cb * 4;

    // --- load recurrent weight slice (rows r=g*4+j, h-cols [256:768)) ---
    {
        for (int it = 0; it < 8; ++it) {
            int f4 = it * 256 + tid;
            int r  = f4 >> 7;
            int k  = (f4 & 127) * 4;
            int gg = r >> 2, j = r & 3;
            const float* Wp = (gg == 0) ? Wf : (gg == 1) ? Wi : (gg == 2) ? Wg : Wo;
            float4 v = *(const float4*)(Wp + (size_t)(u0 + j) * KDH + DIN + k);
            *(float4*)&Ws[r * WS_PITCH + (r >> 3) * 16 + k] = v;
        }
    }
    __syncthreads();

    const int kp = tid & 15;
    const int rq = (tid >> 4) & 1;
    const int bq = tid >> 5;
    const int eb = tid >> 2;
    const int ej = tid & 3;

    const float* wbase = Ws + (rq * 8) * WS_PITCH + rq * 16 + kp;
    const bool hi0 = (kp & 1);
    const bool hi1 = ((kp >> 1) & 1);
    const bool hi2 = ((kp >> 2) & 1);
    const bool hi3 = ((kp >> 3) & 1);

    float c_reg = 0.0f;
    float h_last = 0.0f;

    for (int t = 0; t < T_STEPS; ++t) {
        // prefetch this step's xg contributions (independent of barrier)
        const float* xr = g_xg + (size_t)(t * BATCH + eb) * NGATE4 + u0 + ej;
        float xf = xr[0 * HID], xi = xr[1 * HID], xg2 = xr[2 * HID], xo = xr[3 * HID];

        // ---- acquire: tid0 polls counter, tid0-only fence, then bar.sync ----
        if (t > 0) {
            if (tid == 0) {
                unsigned target = (unsigned)t * 128u;
                while (*(volatile unsigned*)&g_ctr < target) { }
                __threadfence();   // acquire fence, tid0 only
            }
            __syncthreads();
        }

        const float* hin = g_h[t & 1];

        // ---- stage chunk 0 ----
        float4 pre[8];
#pragma unroll
        for (int i = 0; i < 8; ++i) {
            int f4 = i * 256 + tid;
            int b  = f4 >> 5;
            int kq = (f4 & 31) * 4;
            pre[i] = *(const float4*)(hin + b * HID + kq);
        }
#pragma unroll
        for (int i = 0; i < 8; ++i) {
            int f4 = i * 256 + tid;
            int b  = f4 >> 5;
            int kq = (f4 & 31) * 4;
            *(float4*)&hb[b * HP + kq] = pre[i];
        }
        __syncthreads();

        float acc[8][8];
#pragma unroll
        for (int i = 0; i < 8; ++i)
#pragma unroll
            for (int j = 0; j < 8; ++j) acc[i][j] = 0.0f;

        // ---- pipelined K-chunk loop (4 chunks of 128) ----
        for (int c = 0; c < 4; ++c) {
            if (c < 3) {
#pragma unroll
                for (int i = 0; i < 8; ++i) {
                    int f4 = i * 256 + tid;
                    int b  = f4 >> 5;
                    int kq = (f4 & 31) * 4;
                    pre[i] = *(const float4*)(hin + b * HID + (c + 1) * 128 + kq);
                }
            }
            const float* hp = hb + (c & 1) * (64 * HP) + (bq * 8) * HP + kp;
            const float* wp = wbase + c * 128;
#pragma unroll
            for (int g8 = 0; g8 < 8; ++g8) {
                float hv[8], wv[8];
#pragma unroll
                for (int jb = 0; jb < 8; ++jb) hv[jb] = hp[jb * HP + g8 * 16];
#pragma unroll
                for (int jr = 0; jr < 8; ++jr) wv[jr] = wp[jr * WS_PITCH + g8 * 16];
#pragma unroll
                for (int jb = 0; jb < 8; ++jb)
#pragma unroll
                    for (int jr = 0; jr < 8; ++jr)
                        acc[jb][jr] = fmaf(hv[jb], wv[jr], acc[jb][jr]);
            }
            if (c < 3) {
                float* b2 = hb + ((c + 1) & 1) * (64 * HP);
#pragma unroll
                for (int i = 0; i < 8; ++i) {
                    int f4 = i * 256 + tid;
                    int b  = f4 >> 5;
                    int kq = (f4 & 31) * 4;
                    *(float4*)&b2[b * HP + kq] = pre[i];
                }
                __syncthreads();
            }
        }

        // ---- value-splitting butterfly over 16 kp lanes ----
        float a2[4][8];
#pragma unroll
        for (int p = 0; p < 4; ++p)
#pragma unroll
            for (int jr = 0; jr < 8; ++jr) {
                float sv = hi0 ? acc[2 * p][jr] : acc[2 * p + 1][jr];
                float kv = hi0 ? acc[2 * p + 1][jr] : acc[2 * p][jr];
                a2[p][jr] = kv + __shfl_xor_sync(0xffffffffu, sv, 1);
            }
        float a3[2][8];
#pragma unroll
        for (int q = 0; q < 2; ++q)
#pragma unroll
            for (int jr = 0; jr < 8; ++jr) {
                float sv = hi1 ? a2[2 * q][jr] : a2[2 * q + 1][jr];
                float kv = hi1 ? a2[2 * q + 1][jr] : a2[2 * q][jr];
                a3[q][jr] = kv + __shfl_xor_sync(0xffffffffu, sv, 2);
            }
        float a4[8];
#pragma unroll
        for (int jr = 0; jr < 8; ++jr) {
            float sv = hi2 ? a3[0][jr] : a3[1][jr];
            float kv = hi2 ? a3[1][jr] : a3[0][jr];
            a4[jr] = kv + __shfl_xor_sync(0xffffffffu, sv, 4);
        }
        float rr[4];
#pragma unroll
        for (int jrr = 0; jrr < 4; ++jrr) {
            float sv = hi3 ? a4[jrr] : a4[jrr + 4];
            float kv = hi3 ? a4[jrr + 4] : a4[jrr];
            rr[jrr] = kv + __shfl_xor_sync(0xffffffffu, sv, 8);
        }
        {
            int row  = bq * 8 + (kp & 7);
            int col0 = rq * 8 + (kp >> 3) * 4;
#pragma unroll
            for (int jrr = 0; jrr < 4; ++jrr)
                gs[row * GS_PITCH + col0 + jrr] = rr[jrr];
        }
        __syncthreads();

        // ---- elementwise LSTM cell ----
        float pf = gs[eb * GS_PITCH + 0  + ej] + xf;
        float pi = gs[eb * GS_PITCH + 4  + ej] + xi;
        float pg = gs[eb * GS_PITCH + 8  + ej] + xg2;
        float po = gs[eb * GS_PITCH + 12 + ej] + xo;
        float fg = fsigm(pf);
        float ig = fsigm(pi);
        float gg = ftanh(pg);
        float og = fsigm(po);
        c_reg = fg * c_reg + ig * gg;
        float hv = og * ftanh(c_reg);
        h_last = hv;

        // critical-path store first
        g_h[(t + 1) & 1][eb * HID + u0 + ej] = hv;

        // ---- release: bar.sync, then tid0-only fence + atomic signal ----
        __syncthreads();
        if (tid == 0) {
            __threadfence();       // release fence, tid0 only (covers all threads'
            atomicAdd(&g_ctr, 1u); // g_h stores via the preceding bar.sync)
        }

        // off-critical-path output write (next step's consumers don't read it)
        out[(size_t)t * (BATCH * HID) + eb * HID + u0 + ej] = hv;
    }

    const size_t off = (size_t)T_STEPS * BATCH * HID;
    out[off + eb * HID + u0 + ej]               = h_last;
    out[off + BATCH * HID + eb * HID + u0 + ej] = c_reg;
}

extern "C" void kernel_launch(void* const* d_in, const int* in_sizes, int n_in,
                              void* d_out, int out_size) {
    const float* X  = (const float*)d_in[0];
    const float* Wf = (const float*)d_in[1];
    const float* bf = (const float*)d_in[2];
    const float* Wi = (const float*)d_in[3];
    const float* bi = (const float*)d_in[4];
    const float* Wg = (const float*)d_in[5];
    const float* bg = (const float*)d_in[6];
    const float* Wo = (const float*)d_in[7];
    const float* bo = (const float*)d_in[8];
    float* out = (float*)d_out;

    const int smem_bytes = (2 * 64 * HP + 16 * WS_PITCH + 16 + 64 * GS_PITCH) * 4;
    cudaFuncSetAttribute(lstm_rec_kernel,
                         cudaFuncAttributeMaxDynamicSharedMemorySize, smem_bytes);

    init_kernel<<<64, 256>>>();
    xgemm_kernel<<<dim3(16, 256), 256>>>(X, Wf, bf, Wi, bi, Wg, bg, Wo, bo);
    lstm_rec_kernel<<<128, 256, smem_bytes>>>(Wf, Wi, Wg, Wo, out);
}